// round 9
// baseline (speedup 1.0000x reference)
#include <cuda_runtime.h>
#include <cuda_bf16.h>
#include <cstdint>

#define BATCH 2
#define NN 1024
#define ROWS (BATCH * NN)   // 2048
#define SCALE_Y 1.6983709f  // sqrt(2*log2e): t = <yh_i,yh_j> - R_i - R_j = -log2e*q

__device__ __nv_bfloat16 g_Yb[ROWS * 64];  // row-major, 128B rows
__device__ float g_R[ROWS];                // 0.5*||bf16(yh)||^2

__device__ __forceinline__ uint32_t smem_u32(const void* p) {
    uint32_t a;
    asm("{ .reg .u64 t; cvta.to.shared.u64 t, %1; cvt.u32.u64 %0, t; }" : "=r"(a) : "l"(p));
    return a;
}
__device__ __forceinline__ uint32_t swz128(uint32_t off) { return off ^ ((off >> 3) & 0x70); }

__device__ __forceinline__ void ldsm_x4(uint32_t r[4], uint32_t addr) {
    asm volatile("ldmatrix.sync.aligned.m8n8.x4.shared.b16 {%0,%1,%2,%3}, [%4];"
                 : "=r"(r[0]), "=r"(r[1]), "=r"(r[2]), "=r"(r[3]) : "r"(addr));
}
__device__ __forceinline__ void mma16816(float c[4], const uint32_t a[4],
                                         uint32_t b0, uint32_t b1) {
    asm volatile(
        "mma.sync.aligned.m16n8k16.row.col.f32.bf16.bf16.f32 "
        "{%0,%1,%2,%3}, {%4,%5,%6,%7}, {%8,%9}, {%0,%1,%2,%3};"
        : "+f"(c[0]), "+f"(c[1]), "+f"(c[2]), "+f"(c[3])
        : "r"(a[0]), "r"(a[1]), "r"(a[2]), "r"(a[3]), "r"(b0), "r"(b1));
}

// FFMA-only 2^t, deg-4 (abs err ~4e-5 on [-0.5,0.5]); FTZ clamp.
__device__ __forceinline__ float exp2_poly(float tt) {
    const float MAGIC = 12582912.0f;     // 2^23 + 2^22
    const int   MAGIC_I = 0x4B400000;
    float sh = tt + MAGIC;
    float rn = sh - MAGIC;
    float f  = tt - rn;
    int   n  = __float_as_int(sh) - MAGIC_I;
    float p = 9.6181291e-3f;
    p = fmaf(p, f, 5.5504109e-2f);
    p = fmaf(p, f, 2.4022651e-1f);
    p = fmaf(p, f, 6.9314718e-1f);
    p = fmaf(p, f, 1.0f);
    float sc = __int_as_float((n + 127) << 23);
    return (n < -126) ? 0.0f : p * sc;
}

// ---------------------------------------------------------------------------
// Kernel A: yh = SCALE_Y * X @ W, bf16-rounded; R = 0.5*||bf16(yh)||^2.
// ---------------------------------------------------------------------------
__global__ void __launch_bounds__(128) y_kernel(const float* __restrict__ X,
                                                const float* __restrict__ W) {
    __shared__ float Ws[64 * 64];
    __shared__ float Xs[16 * 64];
    const int tid = threadIdx.x;
    const int rowBase = blockIdx.x * 16;

    #pragma unroll
    for (int i = tid; i < 1024; i += 128)
        ((float4*)Ws)[i] = ((const float4*)W)[i];
    #pragma unroll
    for (int i = tid; i < 256; i += 128)
        ((float4*)Xs)[i] = ((const float4*)(X + rowBase * 64))[i];
    __syncthreads();

    const int warp = tid >> 5, lane = tid & 31;
    #pragma unroll
    for (int r = 0; r < 4; r++) {
        const int row = warp * 4 + r;
        float a0 = 0.f, a1 = 0.f;
        #pragma unroll
        for (int c0 = 0; c0 < 64; c0++) {
            const float xv = Xs[row * 64 + c0];
            a0 = fmaf(xv, Ws[c0 * 64 + lane],      a0);
            a1 = fmaf(xv, Ws[c0 * 64 + lane + 32], a1);
        }
        a0 *= SCALE_Y; a1 *= SCALE_Y;
        const __nv_bfloat16 b0 = __float2bfloat16(a0);
        const __nv_bfloat16 b1 = __float2bfloat16(a1);
        const float f0 = __bfloat162float(b0), f1 = __bfloat162float(b1);
        g_Yb[(rowBase + row) * 64 + lane]      = b0;
        g_Yb[(rowBase + row) * 64 + lane + 32] = b1;
        float s = f0 * f0 + f1 * f1;
        #pragma unroll
        for (int o = 16; o; o >>= 1) s += __shfl_xor_sync(0xffffffffu, s, o);
        if (lane == 0) g_R[rowBase + row] = 0.5f * s;
    }
}

// ---------------------------------------------------------------------------
// Kernel B: 128(i) x 64(j) tile, mma.sync bf16, poly-exp epilogue, output via
// STS staging + cp.async.bulk (TMA shared->global). grid (16,8,2), 256 thr.
// Dynamic smem: [0,36864) staging float[128][72] (overlaps A/B operands),
//               [36864, +768) Ri[128],Rj[64].
// ---------------------------------------------------------------------------
#define ST_STRIDE 72
#define SM_STAGE_BYTES (128 * ST_STRIDE * 4)   // 36864
#define SM_TOTAL (SM_STAGE_BYTES + 768)        // 37632

__global__ void __launch_bounds__(256) adj_kernel(float* __restrict__ out) {
    extern __shared__ char sm[];
    __nv_bfloat16* As = (__nv_bfloat16*)sm;               // 16384 B
    __nv_bfloat16* Bs = (__nv_bfloat16*)(sm + 16384);     // 8192 B
    float* stage = (float*)sm;                            // phase-2 reuse
    float* Rish = (float*)(sm + SM_STAGE_BYTES);          // 128 floats
    float* Rjsh = Rish + 128;                             // 64 floats

    const int tid = threadIdx.x;
    const int wid = tid >> 5, lane = tid & 31;
    const int tj = blockIdx.x, ti = blockIdx.y, b = blockIdx.z;

    const int gi = b * NN + ti * 128;
    const int gj = b * NN + tj * 64;

    const uint4* srcA = (const uint4*)(g_Yb + (size_t)gi * 64);
    const uint4* srcB = (const uint4*)(g_Yb + (size_t)gj * 64);
    #pragma unroll
    for (int it = 0; it < 4; it++) {
        const int idx = tid + it * 256;
        const int row = idx >> 3, ch = idx & 7;
        *(uint4*)((char*)As + swz128(row * 128 + ch * 16)) = srcA[idx];
    }
    #pragma unroll
    for (int it = 0; it < 2; it++) {
        const int idx = tid + it * 256;
        const int row = idx >> 3, ch = idx & 7;
        *(uint4*)((char*)Bs + swz128(row * 128 + ch * 16)) = srcB[idx];
    }
    if (tid < 128)       Rish[tid]       = g_R[gi + tid];
    else if (tid < 192)  Rjsh[tid - 128] = g_R[gj + (tid - 128)];
    __syncthreads();

    const uint32_t aBase = smem_u32(As), bBase = smem_u32(Bs);
    const int mrow0 = wid * 16;

    float acc[8][4];
    #pragma unroll
    for (int nb = 0; nb < 8; nb++)
        #pragma unroll
        for (int k = 0; k < 4; k++) acc[nb][k] = 0.f;

    #pragma unroll
    for (int ks = 0; ks < 4; ks++) {
        uint32_t a[4];
        {
            const int arow = mrow0 + ((lane >> 3) & 1) * 8 + (lane & 7);
            const int kb   = ks * 32 + (lane >> 4) * 16;
            ldsm_x4(a, aBase + swz128(arow * 128 + kb));
        }
        #pragma unroll
        for (int nb2 = 0; nb2 < 4; nb2++) {
            uint32_t bf[4];
            const int nrow = nb2 * 16 + ((lane >> 4) & 1) * 8 + (lane & 7);
            const int kb   = ks * 32 + ((lane >> 3) & 1) * 16;
            ldsm_x4(bf, bBase + swz128(nrow * 128 + kb));
            mma16816(acc[nb2 * 2],     a, bf[0], bf[1]);
            mma16816(acc[nb2 * 2 + 1], a, bf[2], bf[3]);
        }
    }
    __syncthreads();   // A/B reads done everywhere; staging may now overwrite

    // Epilogue: exp + STS.64 into staging [row][col], stride 72 floats.
    const int rloc = lane >> 2;
    const float ri0 = Rish[mrow0 + rloc];
    const float ri1 = Rish[mrow0 + 8 + rloc];
    const bool diagTile = (ti * 2 == tj || ti * 2 + 1 == tj);
    const int colOff = tj * 64;
    const int r0 = mrow0 + rloc, r1 = r0 + 8;

    #pragma unroll
    for (int nb = 0; nb < 8; nb++) {
        const int col0 = nb * 8 + (lane & 3) * 2;
        const float rj0 = Rjsh[col0], rj1 = Rjsh[col0 + 1];
        float e00 = exp2_poly((acc[nb][0] - ri0) - rj0);
        float e01 = exp2_poly((acc[nb][1] - ri0) - rj1);
        float e10 = exp2_poly((acc[nb][2] - ri1) - rj0);
        float e11 = exp2_poly((acc[nb][3] - ri1) - rj1);
        if (diagTile) {
            const int grow0 = ti * 128 + r0;
            const int gcol0 = colOff + col0;
            if (grow0 == gcol0)         e00 = 2.0f;
            if (grow0 == gcol0 + 1)     e01 = 2.0f;
            if (grow0 + 8 == gcol0)     e10 = 2.0f;
            if (grow0 + 8 == gcol0 + 1) e11 = 2.0f;
        }
        *(float2*)&stage[r0 * ST_STRIDE + col0] = make_float2(e00, e01);
        *(float2*)&stage[r1 * ST_STRIDE + col0] = make_float2(e10, e11);
    }
    __syncthreads();

    // TMA bulk store: one 256B row per thread (tid < 128).
    asm volatile("fence.proxy.async.shared::cta;" ::: "memory");
    if (tid < 128) {
        const size_t outBase = (size_t)b * NN * NN;
        const float* dst = out + outBase + (size_t)(ti * 128 + tid) * NN + colOff;
        const uint32_t src = smem_u32(stage + tid * ST_STRIDE);
        asm volatile("cp.async.bulk.global.shared::cta.bulk_group [%0], [%1], %2;"
                     :: "l"(dst), "r"(src), "r"(256u) : "memory");
        asm volatile("cp.async.bulk.commit_group;" ::: "memory");
        asm volatile("cp.async.bulk.wait_group 0;" ::: "memory");
    }
}

// ---------------------------------------------------------------------------
extern "C" void kernel_launch(void* const* d_in, const int* in_sizes, int n_in,
                              void* d_out, int out_size) {
    const float* X = (const float*)d_in[0];   // (2,1024,64)
    const float* W = (const float*)d_in[1];   // (64,64)
    float* out = (float*)d_out;               // (2,1024,1024)

    static int attr_set = 0;
    if (!attr_set) {
        cudaFuncSetAttribute(adj_kernel, cudaFuncAttributeMaxDynamicSharedMemorySize, SM_TOTAL);
        attr_set = 1;
    }

    y_kernel<<<128, 128>>>(X, W);
    adj_kernel<<<dim3(16, 8, 2), 256, SM_TOTAL>>>(out);
    (void)in_sizes; (void)n_in; (void)out_size;
}

// round 10
// speedup vs baseline: 1.1493x; 1.1493x over previous
#include <cuda_runtime.h>
#include <cuda_bf16.h>
#include <cstdint>

#define BATCH 2
#define NN 1024
#define ROWS (BATCH * NN)   // 2048
#define SCALE_Y 1.6983709f  // sqrt(2*log2e): t = <yh_i,yh_j> - R_i - R_j = -log2e*q

__device__ __nv_bfloat16 g_Yb[ROWS * 64];  // row-major, 128B rows
__device__ float g_R[ROWS];                // 0.5*||bf16(yh)||^2

__device__ __forceinline__ uint32_t smem_u32(const void* p) {
    uint32_t a;
    asm("{ .reg .u64 t; cvta.to.shared.u64 t, %1; cvt.u32.u64 %0, t; }" : "=r"(a) : "l"(p));
    return a;
}
__device__ __forceinline__ uint32_t swz128(uint32_t off) { return off ^ ((off >> 3) & 0x70); }

__device__ __forceinline__ void ldsm_x4(uint32_t r[4], uint32_t addr) {
    asm volatile("ldmatrix.sync.aligned.m8n8.x4.shared.b16 {%0,%1,%2,%3}, [%4];"
                 : "=r"(r[0]), "=r"(r[1]), "=r"(r[2]), "=r"(r[3]) : "r"(addr));
}
__device__ __forceinline__ void mma16816(float c[4], const uint32_t a[4],
                                         uint32_t b0, uint32_t b1) {
    asm volatile(
        "mma.sync.aligned.m16n8k16.row.col.f32.bf16.bf16.f32 "
        "{%0,%1,%2,%3}, {%4,%5,%6,%7}, {%8,%9}, {%0,%1,%2,%3};"
        : "+f"(c[0]), "+f"(c[1]), "+f"(c[2]), "+f"(c[3])
        : "r"(a[0]), "r"(a[1]), "r"(a[2]), "r"(a[3]), "r"(b0), "r"(b1));
}

// FFMA-only 2^t, deg-4 (abs err ~4e-5 on [-0.5,0.5]); FTZ clamp.
__device__ __forceinline__ float exp2_poly(float tt) {
    const float MAGIC = 12582912.0f;     // 2^23 + 2^22
    const int   MAGIC_I = 0x4B400000;
    float sh = tt + MAGIC;
    float rn = sh - MAGIC;
    float f  = tt - rn;
    int   n  = __float_as_int(sh) - MAGIC_I;
    float p = 9.6181291e-3f;
    p = fmaf(p, f, 5.5504109e-2f);
    p = fmaf(p, f, 2.4022651e-1f);
    p = fmaf(p, f, 6.9314718e-1f);
    p = fmaf(p, f, 1.0f);
    float sc = __int_as_float((n + 127) << 23);
    return (n < -126) ? 0.0f : p * sc;
}

// ---------------------------------------------------------------------------
// Kernel A: yh = SCALE_Y * X @ W, bf16-rounded; R = 0.5*||bf16(yh)||^2.
// ---------------------------------------------------------------------------
__global__ void __launch_bounds__(128) y_kernel(const float* __restrict__ X,
                                                const float* __restrict__ W) {
    __shared__ float Ws[64 * 64];
    __shared__ float Xs[16 * 64];
    const int tid = threadIdx.x;
    const int rowBase = blockIdx.x * 16;

    #pragma unroll
    for (int i = tid; i < 1024; i += 128)
        ((float4*)Ws)[i] = ((const float4*)W)[i];
    #pragma unroll
    for (int i = tid; i < 256; i += 128)
        ((float4*)Xs)[i] = ((const float4*)(X + rowBase * 64))[i];
    __syncthreads();

    const int warp = tid >> 5, lane = tid & 31;
    #pragma unroll
    for (int r = 0; r < 4; r++) {
        const int row = warp * 4 + r;
        float a0 = 0.f, a1 = 0.f;
        #pragma unroll
        for (int c0 = 0; c0 < 64; c0++) {
            const float xv = Xs[row * 64 + c0];
            a0 = fmaf(xv, Ws[c0 * 64 + lane],      a0);
            a1 = fmaf(xv, Ws[c0 * 64 + lane + 32], a1);
        }
        a0 *= SCALE_Y; a1 *= SCALE_Y;
        const __nv_bfloat16 b0 = __float2bfloat16(a0);
        const __nv_bfloat16 b1 = __float2bfloat16(a1);
        const float f0 = __bfloat162float(b0), f1 = __bfloat162float(b1);
        g_Yb[(rowBase + row) * 64 + lane]      = b0;
        g_Yb[(rowBase + row) * 64 + lane + 32] = b1;
        float s = f0 * f0 + f1 * f1;
        #pragma unroll
        for (int o = 16; o; o >>= 1) s += __shfl_xor_sync(0xffffffffu, s, o);
        if (lane == 0) g_R[rowBase + row] = 0.5f * s;
    }
}

// ---------------------------------------------------------------------------
// Kernel B: 64(i) x 64(j) tile, 128 threads (4 warps), mma.sync bf16,
// poly-exp epilogue, direct register STG. grid (tj=16, ti=16, b=2) = 512.
// Warp w computes rows [w*16, w*16+16) x 64 cols.
// ---------------------------------------------------------------------------
__global__ void __launch_bounds__(128) adj_kernel(float* __restrict__ out) {
    __shared__ __align__(1024) __nv_bfloat16 As[64 * 64];
    __shared__ __align__(1024) __nv_bfloat16 Bs[64 * 64];
    __shared__ float Rish[64], Rjsh[64];

    const int tid = threadIdx.x;
    const int wid = tid >> 5, lane = tid & 31;
    const int tj = blockIdx.x, ti = blockIdx.y, b = blockIdx.z;

    const int gi = b * NN + ti * 64;
    const int gj = b * NN + tj * 64;

    // Global -> swizzled smem: 512 x 16B chunks each, 4 per thread.
    const uint4* srcA = (const uint4*)(g_Yb + (size_t)gi * 64);
    const uint4* srcB = (const uint4*)(g_Yb + (size_t)gj * 64);
    #pragma unroll
    for (int it = 0; it < 4; it++) {
        const int idx = tid + it * 128;
        const int row = idx >> 3, ch = idx & 7;
        const uint32_t sw = swz128(row * 128 + ch * 16);
        *(uint4*)((char*)As + sw) = srcA[idx];
        *(uint4*)((char*)Bs + sw) = srcB[idx];
    }
    if (tid < 64)        Rish[tid]      = g_R[gi + tid];
    else                 Rjsh[tid - 64] = g_R[gj + (tid - 64)];
    __syncthreads();

    const uint32_t aBase = smem_u32(As), bBase = smem_u32(Bs);
    const int mrow0 = wid * 16;

    float acc[8][4];
    #pragma unroll
    for (int nb = 0; nb < 8; nb++)
        #pragma unroll
        for (int k = 0; k < 4; k++) acc[nb][k] = 0.f;

    #pragma unroll
    for (int ks = 0; ks < 4; ks++) {
        uint32_t a[4];
        {
            const int arow = mrow0 + ((lane >> 3) & 1) * 8 + (lane & 7);
            const int kb   = ks * 32 + (lane >> 4) * 16;
            ldsm_x4(a, aBase + swz128(arow * 128 + kb));
        }
        #pragma unroll
        for (int nb2 = 0; nb2 < 4; nb2++) {
            uint32_t bf[4];
            const int nrow = nb2 * 16 + ((lane >> 4) & 1) * 8 + (lane & 7);
            const int kb   = ks * 32 + ((lane >> 3) & 1) * 16;
            ldsm_x4(bf, bBase + swz128(nrow * 128 + kb));
            mma16816(acc[nb2 * 2],     a, bf[0], bf[1]);
            mma16816(acc[nb2 * 2 + 1], a, bf[2], bf[3]);
        }
    }

    // Epilogue + direct stores. Accum m16n8: c0,c1 @ (row=lane>>2,
    // col=(lane&3)*2+{0,1}), c2,c3 @ row+8.
    const int rloc = lane >> 2;
    const float ri0 = Rish[mrow0 + rloc];
    const float ri1 = Rish[mrow0 + 8 + rloc];
    const bool diagTile = (ti == tj);
    const size_t outBase = (size_t)b * NN * NN;
    const int gRow0 = ti * 64 + mrow0 + rloc;
    const size_t o0 = outBase + (size_t)gRow0 * NN + tj * 64;
    const size_t o1 = o0 + 8u * NN;

    #pragma unroll
    for (int nb = 0; nb < 8; nb++) {
        const int col0 = nb * 8 + (lane & 3) * 2;
        const float rj0 = Rjsh[col0], rj1 = Rjsh[col0 + 1];
        float e00 = exp2_poly((acc[nb][0] - ri0) - rj0);
        float e01 = exp2_poly((acc[nb][1] - ri0) - rj1);
        float e10 = exp2_poly((acc[nb][2] - ri1) - rj0);
        float e11 = exp2_poly((acc[nb][3] - ri1) - rj1);
        if (diagTile) {
            const int lrow0 = mrow0 + rloc, lrow1 = lrow0 + 8;
            if (lrow0 == col0)     e00 = 2.0f;
            if (lrow0 == col0 + 1) e01 = 2.0f;
            if (lrow1 == col0)     e10 = 2.0f;
            if (lrow1 == col0 + 1) e11 = 2.0f;
        }
        *(float2*)&out[o0 + col0] = make_float2(e00, e01);
        *(float2*)&out[o1 + col0] = make_float2(e10, e11);
    }
}

// ---------------------------------------------------------------------------
extern "C" void kernel_launch(void* const* d_in, const int* in_sizes, int n_in,
                              void* d_out, int out_size) {
    const float* X = (const float*)d_in[0];   // (2,1024,64)
    const float* W = (const float*)d_in[1];   // (64,64)
    float* out = (float*)d_out;               // (2,1024,1024)

    y_kernel<<<128, 128>>>(X, W);
    adj_kernel<<<dim3(16, 16, 2), 128>>>(out);
    (void)in_sizes; (void)n_in; (void)out_size;
}